// round 4
// baseline (speedup 1.0000x reference)
#include <cuda_runtime.h>
#include <cuda_bf16.h>
#include <math.h>

// Problem constants
#define VV   32000
#define EE   500
#define HH   500
#define DD1  800
#define DD2  100
#define CC   2
#define BB   64
#define TT   400
#define G4H  2000            // 4*H
#define MM   (BB*TT)         // 25600 rows of the big GEMMs
#define NREC_BLOCKS 125      // 125 * 4 units = 500
#define HPAD 512             // padded hidden for float4 staging

// ---------------- scratch (device globals; no allocation allowed) ----------------
__device__ float g_xz [(size_t)MM * G4H];     // 204.8 MB, reused for layer1 and layer2
__device__ float g_hs1[(size_t)MM * HH];      // 51.2 MB
__device__ float g_hb0[HPAD * BB];
__device__ float g_hb1[HPAD * BB];
__device__ float g_d1 [BB * DD1];
__device__ float g_d2 [BB * DD2];
__device__ unsigned long long g_bar_cnt   = 0;
__device__ unsigned long long g_bar_sense = 0;

// ---------------- packed f32x2 helpers ----------------
__device__ __forceinline__ unsigned long long pk2(float lo, float hi){
    unsigned long long r;
    asm("mov.b64 %0, {%1, %2};" : "=l"(r) : "f"(lo), "f"(hi));
    return r;
}
__device__ __forceinline__ unsigned long long dup2(float v){
    unsigned long long r;
    asm("mov.b64 %0, {%1, %1};" : "=l"(r) : "f"(v));
    return r;
}
__device__ __forceinline__ void fma2(unsigned long long &d,
                                     unsigned long long a,
                                     unsigned long long b){
    asm("fma.rn.f32x2 %0, %1, %2, %3;" : "=l"(d) : "l"(a), "l"(b), "l"(d));
}
__device__ __forceinline__ void unpk2(unsigned long long v, float &lo, float &hi){
    asm("mov.b64 {%0, %1}, %2;" : "=f"(lo), "=f"(hi) : "l"(v));
}

// =====================================================================
// SGEMM: C[M=25600, N=2000] = A[M,500] @ Bw[500,2000] + bias
// GATHER=1: A row m -> embed[X[b*T+t]] with m = t*64+b
// 128x128 block tile, BK=8, 256 threads, 8x8 per-thread tile, f32x2 math
// =====================================================================
template<int GATHER>
__global__ __launch_bounds__(256)
void sgemm_xz(const int* __restrict__ X, const float* __restrict__ A,
              const float* __restrict__ Bw, const float* __restrict__ bias,
              float* __restrict__ Cmat)
{
    __shared__ float As[8][128];
    __shared__ float Bs[8][128];

    const int tid = threadIdx.x;
    const int tx  = tid & 15;        // 0..15 -> 8 cols each
    const int ty  = tid >> 4;        // 0..15 -> 8 rows each
    const int m0  = blockIdx.y * 128;
    const int n0  = blockIdx.x * 128;

    // A tile loader: row = tid>>1 (0..127), k-quad = (tid&1)*4
    const int ar  = tid >> 1;
    const int akq = (tid & 1) * 4;
    const float* arow_ptr;
    {
        int m = m0 + ar;
        if (GATHER){
            int t = m >> 6, b = m & 63;
            int tok = X[b * TT + t];
            arow_ptr = A + (size_t)tok * EE;
        } else {
            arow_ptr = A + (size_t)m * HH;
        }
    }
    // B tile loader: k-row = tid>>5 (0..7), n-quad = (tid&31)*4
    const int bk = tid >> 5;
    const int bn = (tid & 31) * 4;

    unsigned long long acc[8][4];
    #pragma unroll
    for (int i = 0; i < 8; i++)
        #pragma unroll
        for (int j = 0; j < 4; j++) acc[i][j] = 0ULL;   // bits of (0.f,0.f)

    const float4 f40 = make_float4(0.f, 0.f, 0.f, 0.f);
    float4 aReg, bReg;
    {   // prefetch tile 0
        int k  = akq;
        aReg = (k < 500) ? *(const float4*)(arow_ptr + k) : f40;
        int kb = bk, n = n0 + bn;
        bReg = (kb < 500 && n < G4H) ? *(const float4*)(Bw + (size_t)kb * G4H + n) : f40;
    }

    const int KT = 63;   // ceil(500/8)
    for (int kt = 0; kt < KT; kt++){
        __syncthreads();
        As[akq+0][ar] = aReg.x; As[akq+1][ar] = aReg.y;
        As[akq+2][ar] = aReg.z; As[akq+3][ar] = aReg.w;
        *(float4*)(&Bs[bk][bn]) = bReg;
        __syncthreads();

        if (kt + 1 < KT){   // prefetch next tile into registers
            int k = (kt+1)*8 + akq;
            aReg = (k < 500) ? *(const float4*)(arow_ptr + k) : f40;
            int kb = (kt+1)*8 + bk, n = n0 + bn;
            bReg = (kb < 500 && n < G4H) ? *(const float4*)(Bw + (size_t)kb * G4H + n) : f40;
        }

        #pragma unroll
        for (int kk = 0; kk < 8; kk++){
            float4 a0 = *(const float4*)(&As[kk][ty*8]);
            float4 a1 = *(const float4*)(&As[kk][ty*8 + 4]);
            const unsigned long long* bp2 = (const unsigned long long*)(&Bs[kk][tx*8]);
            unsigned long long b0 = bp2[0], b1 = bp2[1], b2 = bp2[2], b3 = bp2[3];
            float av[8] = {a0.x,a0.y,a0.z,a0.w,a1.x,a1.y,a1.z,a1.w};
            #pragma unroll
            for (int i = 0; i < 8; i++){
                unsigned long long ad = dup2(av[i]);
                fma2(acc[i][0], ad, b0);
                fma2(acc[i][1], ad, b1);
                fma2(acc[i][2], ad, b2);
                fma2(acc[i][3], ad, b3);
            }
        }
    }

    // epilogue: +bias, store
    const int nc = n0 + tx * 8;
    if (nc < G4H){
        float4 bb0 = *(const float4*)(bias + nc);
        float4 bb1 = *(const float4*)(bias + nc + 4);
        #pragma unroll
        for (int i = 0; i < 8; i++){
            int m = m0 + ty*8 + i;
            float o[8];
            unpk2(acc[i][0], o[0], o[1]);
            unpk2(acc[i][1], o[2], o[3]);
            unpk2(acc[i][2], o[4], o[5]);
            unpk2(acc[i][3], o[6], o[7]);
            float4 r0 = make_float4(o[0]+bb0.x, o[1]+bb0.y, o[2]+bb0.z, o[3]+bb0.w);
            float4 r1 = make_float4(o[4]+bb1.x, o[5]+bb1.y, o[6]+bb1.z, o[7]+bb1.w);
            float* cp = Cmat + (size_t)m * G4H + nc;
            *(float4*)(cp)     = r0;
            *(float4*)(cp + 4) = r1;
        }
    }
}

// =====================================================================
// Persistent LSTM recurrence.
// Grid: 125 blocks x 256 threads. thread = (b = tid&63, u = tid>>6); block owns
// 4 hidden units. Wh slice cached in SMEM (500 x 4units x 4gates), h_prev staged
// to SMEM each step via __ldcg. Grid-wide sense-reversing barrier, 1/step.
// 125 blocks x 163KB smem -> exactly 1 block/SM, all co-resident (148 SMs).
// =====================================================================
__device__ __forceinline__ void grid_barrier(int nb, unsigned long long* s_sense)
{
    __threadfence();          // make this thread's .cg stores device-visible
    __syncthreads();
    if (threadIdx.x == 0){
        unsigned long long pos = atomicAdd(&g_bar_cnt, 1ULL);
        if (pos == (unsigned long long)(nb - 1)){
            atomicExch(&g_bar_cnt, 0ULL);
            __threadfence();
            atomicAdd(&g_bar_sense, 1ULL);
            *s_sense += 1ULL;
        } else {
            unsigned long long target = *s_sense + 1ULL;
            while (*((volatile unsigned long long*)&g_bar_sense) < target) {
                __nanosleep(64);
            }
            *s_sense = target;
        }
    }
    __syncthreads();
}

__global__ void lstm_rec(const float* __restrict__ xz, const float* __restrict__ Wh,
                         float* __restrict__ hs_out, int store_hs,
                         float* __restrict__ hb0, float* __restrict__ hb1, int nb)
{
    extern __shared__ float smem[];
    float* hsm = smem;                              // HPAD*64 floats (128 KB)
    float* wsm = smem + HPAD * BB;                  // 500*16 floats (32 KB)
    __shared__ unsigned long long s_sense;

    const int tid = threadIdx.x;
    const int b   = tid & 63;
    const int u   = tid >> 6;          // 0..3
    const int u0  = blockIdx.x * 4;
    const int uu  = u0 + u;            // this thread's hidden unit

    if (tid == 0) s_sense = *((volatile unsigned long long*)&g_bar_sense);

    // cache weight slice: wsm[k*16 + uw*4 + g] = Wh[k*2000 + g*500 + u0+uw]
    for (int idx = tid; idx < 500 * 16; idx += 256){
        int k = idx >> 4, r = idx & 15;
        int uw = r >> 2, g = r & 3;
        wsm[idx] = Wh[(size_t)k * G4H + g * HH + u0 + uw];
    }

    // zero both h buffers (incl. pad rows, stay zero forever)
    {
        int gt = blockIdx.x * 256 + tid;
        float4 z4 = make_float4(0.f, 0.f, 0.f, 0.f);
        for (int i = gt; i < (HPAD * BB) / 4; i += nb * 256){
            ((float4*)hb0)[i] = z4;
            ((float4*)hb1)[i] = z4;
        }
    }
    grid_barrier(nb, &s_sense);   // weights loaded + buffers zeroed everywhere

    const unsigned long long* wp2 = (const unsigned long long*)wsm;
    float c = 0.f;

    for (int t = 0; t < TT; t++){
        const float* hprev = (t & 1) ? hb1 : hb0;
        float*       hnext = (t & 1) ? hb0 : hb1;

        // stage h_prev (layout [unit*64 + b]) into SMEM, bypassing L1
        for (int i = tid; i < (HPAD * BB) / 4; i += 256)
            ((float4*)hsm)[i] = __ldcg(((const float4*)hprev) + i);

        // pre-issue the xz loads (overlap with staging)
        size_t mrow = (size_t)(t * BB + b) * G4H + uu;
        float xi = __ldcs(xz + mrow);
        float xj = __ldcs(xz + mrow + 500);
        float xf = __ldcs(xz + mrow + 1000);
        float xo = __ldcs(xz + mrow + 1500);
        __syncthreads();

        unsigned long long aij = pk2(xi, xj);
        unsigned long long afo = pk2(xf, xo);
        #pragma unroll 4
        for (int k = 0; k < 500; k++){
            unsigned long long hh  = dup2(hsm[k * 64 + b]);
            unsigned long long wij = wp2[(k * 4 + u) * 2];
            unsigned long long wfo = wp2[(k * 4 + u) * 2 + 1];
            fma2(aij, hh, wij);
            fma2(afo, hh, wfo);
        }
        float zi, zj, zf, zo;
        unpk2(aij, zi, zj);
        unpk2(afo, zf, zo);

        float ig = 1.f / (1.f + expf(-zi));
        float fg = 1.f / (1.f + expf(-(zf + 1.f)));
        float og = 1.f / (1.f + expf(-zo));
        float jt = tanhf(zj);
        c = fg * c + ig * jt;
        float hv = og * tanhf(c);

        __stcg(hnext + uu * 64 + b, hv);
        if (store_hs)
            hs_out[(size_t)(t * BB + b) * HH + uu] = hv;

        grid_barrier(nb, &s_sense);
    }
}

// =====================================================================
// Small dense layers. out[b*N + j] = act(sum_k in(b,k)*W[k*N+j] + bias[j])
// transposed_in: in[k*64 + b]  (final LSTM h layout), else in[b*K + k]
// =====================================================================
__global__ void dense_kernel(const float* __restrict__ in, const float* __restrict__ W,
                             const float* __restrict__ bias, float* __restrict__ out,
                             int Kdim, int Ndim, int transposed_in, int do_relu)
{
    int g = blockIdx.x * blockDim.x + threadIdx.x;
    if (g >= BB * Ndim) return;
    int bv = g / Ndim;
    int j  = g - bv * Ndim;
    float acc = bias[j];
    if (transposed_in){
        for (int k = 0; k < Kdim; k++)
            acc += in[k * 64 + bv] * W[k * Ndim + j];
    } else {
        for (int k = 0; k < Kdim; k++)
            acc += in[bv * Kdim + k] * W[k * Ndim + j];
    }
    out[g] = do_relu ? fmaxf(acc, 0.f) : acc;
}

// =====================================================================
// Launch
// =====================================================================
#define REC_SMEM ((HPAD*BB + 500*16) * (int)sizeof(float))   // 163072 B

extern "C" void kernel_launch(void* const* d_in, const int* in_sizes, int n_in,
                              void* d_out, int out_size)
{
    const int*   X     = (const int*)  d_in[0];
    const float* embed = (const float*)d_in[1];
    const float* k1    = (const float*)d_in[2];
    const float* b1    = (const float*)d_in[3];
    const float* k2    = (const float*)d_in[4];
    const float* b2    = (const float*)d_in[5];
    const float* w1    = (const float*)d_in[6];
    const float* bw1   = (const float*)d_in[7];
    const float* w2    = (const float*)d_in[8];
    const float* bw2   = (const float*)d_in[9];
    const float* wp    = (const float*)d_in[10];
    const float* bp    = (const float*)d_in[11];
    float* out = (float*)d_out;

    float *xz, *hs1, *hb0, *hb1, *d1, *d2;
    cudaGetSymbolAddress((void**)&xz,  g_xz);
    cudaGetSymbolAddress((void**)&hs1, g_hs1);
    cudaGetSymbolAddress((void**)&hb0, g_hb0);
    cudaGetSymbolAddress((void**)&hb1, g_hb1);
    cudaGetSymbolAddress((void**)&d1,  g_d1);
    cudaGetSymbolAddress((void**)&d2,  g_d2);

    cudaFuncSetAttribute(lstm_rec, cudaFuncAttributeMaxDynamicSharedMemorySize, REC_SMEM);

    dim3 ggrid(16, 200);   // N tiles x M tiles

    // layer 1: xz1 = embed[X] @ k1[:E] + b1 ; then recurrence (stores hs1)
    sgemm_xz<1><<<ggrid, 256>>>(X, embed, k1, b1, xz);
    lstm_rec<<<NREC_BLOCKS, 256, REC_SMEM>>>(xz, k1 + (size_t)EE * G4H,
                                             hs1, 1, hb0, hb1, NREC_BLOCKS);

    // layer 2: xz2 = hs1 @ k2[:H] + b2 ; recurrence (final h only)
    sgemm_xz<0><<<ggrid, 256>>>(nullptr, hs1, k2, b2, xz);
    lstm_rec<<<NREC_BLOCKS, 256, REC_SMEM>>>(xz, k2 + (size_t)HH * G4H,
                                             nullptr, 0, hb0, hb1, NREC_BLOCKS);

    // head: T=400 is even, so final h lives in hb0 (written at t=399)
    dense_kernel<<<(BB*DD1 + 255)/256, 256>>>(hb0, w1, bw1, d1, HH,  DD1, 1, 1);
    dense_kernel<<<(BB*DD2 + 255)/256, 256>>>(d1,  w2, bw2, d2, DD1, DD2, 0, 1);
    dense_kernel<<<1, BB*CC>>>(d2, wp, bp, out, DD2, CC, 0, 0);
}